// round 11
// baseline (speedup 1.0000x reference)
#include <cuda_runtime.h>
#include <cstdint>

// SigmoidFlow, quad-split compute + cp.async double-buffered SMEM pipeline.
//
// Math (linear-domain collapse of the reference):
//   logj = log( sum_k e_k * a_k * s_k(1-s_k) ) - log( sum_k e_k ), e_k=exp(wl_k)
//   s(1-s) = u*r^2, u = exp(-|pre|), r = 1/(1+u)  (both signs).
//
// R10: dsparams streamed gmem->smem with cp.async.cg (deep MLP independent of
// register file, perfectly coalesced), 2-stage double buffer, compute reads
// tiles from SMEM. 4 threads cooperate per element (4 k's each).

#define NDIM 16
#define DELTA_F 1e-6f
#define LOG1MDELTA (-1.0000005e-6f)   // log(1 - 1e-6)

#define TILE_ELEMS 128
#define TILE_F4    (TILE_ELEMS * 12)   // 1536 float4 = 24 KB
#define THREADS    512

__device__ __forceinline__ void cp_async16(uint32_t dst_smem, const float4* src) {
    asm volatile("cp.async.cg.shared.global [%0], [%1], 16;"
                 :: "r"(dst_smem), "l"(src));
}
__device__ __forceinline__ void cp_commit() {
    asm volatile("cp.async.commit_group;");
}
__device__ __forceinline__ void cp_wait1() {
    asm volatile("cp.async.wait_group 1;");
}
__device__ __forceinline__ void cp_wait0() {
    asm volatile("cp.async.wait_group 0;");
}

__global__ __launch_bounds__(THREADS, 3)
void sigmoid_flow_kernel(const float* __restrict__ x,
                         const float* __restrict__ logdet_in,
                         const float* __restrict__ dsp,
                         float* __restrict__ out_xnew,
                         float* __restrict__ out_logdet,
                         int D)
{
    extern __shared__ float4 sbuf[];          // 2 * TILE_F4 float4s
    __shared__ float sred[16];

    const int b = blockIdx.x;
    const int t = threadIdx.x;
    const int q = t >> 2;                     // element slot in tile (0..127)
    const int c = t & 3;                      // float4 chunk of element (0..3)
    const int ntiles = D / TILE_ELEMS;        // 4 for D=512

    const float4* __restrict__ dsp4 = reinterpret_cast<const float4*>(dsp);
    const uint32_t smem_base = (uint32_t)__cvta_generic_to_shared(sbuf);

    // ---- stage a tile of dsparams into smem buffer (coalesced, async) ----
    auto stage = [&](int tile, int bufsel) {
        const float4* src = dsp4 + (long long)(b * D + tile * TILE_ELEMS) * 12;
        const uint32_t dst = smem_base + (uint32_t)bufsel * (TILE_F4 * 16);
#pragma unroll
        for (int i = 0; i < TILE_F4 / THREADS; i++) {
            const int idx = t + i * THREADS;
            cp_async16(dst + idx * 16, src + idx);
        }
        cp_commit();
    };

    // prologue: prefetch tiles 0 and 1
    stage(0, 0);
    if (ntiles > 1) stage(1, 1);

    float ldsum = 0.0f;

    for (int tile = 0; tile < ntiles; tile++) {
        if (tile + 2 <= ntiles) cp_wait1(); else cp_wait0();
        __syncthreads();

        const float4* buf = sbuf + (tile & 1) * TILE_F4;
        const int e = b * D + tile * TILE_ELEMS + q;

        const float4 va = buf[q * 12 + c];
        const float4 vb = buf[q * 12 + 4 + c];
        const float4 vw = buf[q * 12 + 8 + c];
        const float xv = x[e];

        const float zs[4] = {va.x, va.y, va.z, va.w};
        const float bs[4] = {vb.x, vb.y, vb.z, vb.w};
        const float ws[4] = {vw.x, vw.y, vw.z, vw.w};

        float Se = 0.0f, S1 = 0.0f, S2 = 0.0f;
#pragma unroll
        for (int j = 0; j < 4; j++) {
            // a = softplus(z), numerically stable
            const float z = zs[j];
            const float tt = __expf(-fabsf(z));
            const float a = fmaxf(z, 0.0f) + __logf(1.0f + tt);

            // sigmoid terms via shared exp(-|pre|)
            const float pre = fmaf(a, xv, bs[j]);
            const float u = __expf(-fabsf(pre));
            const float r = __fdividef(1.0f, 1.0f + u);
            const float s = (pre > 0.0f) ? r : u * r;  // sigmoid(pre)
            const float ss = u * r * r;                // sigm(pre)*sigm(-pre)

            const float ek = __expf(ws[j]);            // unnormalized softmax

            Se += ek;
            S1 = fmaf(ek, s, S1);
            S2 = fmaf(ek * a, ss, S2);
        }

        // reduce the three sums across the quad
        Se += __shfl_xor_sync(0xffffffffu, Se, 1);
        Se += __shfl_xor_sync(0xffffffffu, Se, 2);
        S1 += __shfl_xor_sync(0xffffffffu, S1, 1);
        S1 += __shfl_xor_sync(0xffffffffu, S1, 2);
        S2 += __shfl_xor_sync(0xffffffffu, S2, 1);
        S2 += __shfl_xor_sync(0xffffffffu, S2, 2);

        // epilogue: computed by all quad lanes (no divergence), stored by c==0
        const float invSe = __fdividef(1.0f, Se);
        const float x_pre = S1 * invSe;
        const float xpc = fmaf(x_pre, 1.0f - DELTA_F, 0.5f * DELTA_F);
        const float lx  = __logf(xpc);
        const float l1x = __logf(1.0f - xpc);
        const float logj = __logf(S2 * invSe);

        if (c == 0) {
            out_xnew[e] = lx - l1x;
            ldsum += logj + LOG1MDELTA - lx - l1x;
        }

        __syncthreads();   // all reads of buf done before it is re-staged
        if (tile + 2 < ntiles) stage(tile + 2, tile & 1);
    }

    // ---- deterministic block reduction for logdet (no float atomics) ----
    const int lane = t & 31;
    const int warp = t >> 5;
#pragma unroll
    for (int o = 16; o > 0; o >>= 1)
        ldsum += __shfl_xor_sync(0xffffffffu, ldsum, o);

    if (lane == 0) sred[warp] = ldsum;
    __syncthreads();

    if (warp == 0) {
        float v = (lane < 16) ? sred[lane] : 0.0f;
#pragma unroll
        for (int o = 16; o > 0; o >>= 1)
            v += __shfl_xor_sync(0xffffffffu, v, o);
        if (lane == 0)
            out_logdet[b] = v + logdet_in[b];
    }
}

extern "C" void kernel_launch(void* const* d_in, const int* in_sizes, int n_in,
                              void* d_out, int out_size)
{
    const float* x         = (const float*)d_in[0];   // (B, D)
    const float* logdet_in = (const float*)d_in[1];   // (B,)
    const float* dsp       = (const float*)d_in[2];   // (B, D, 3*NDIM)

    const int B = in_sizes[1];
    const int D = in_sizes[0] / B;   // 512

    float* out_xnew   = (float*)d_out;                      // (B, D)
    float* out_logdet = (float*)d_out + (size_t)B * D;      // (B,)

    const int smem_bytes = 2 * TILE_F4 * (int)sizeof(float4);   // 49152
    static bool attr_set = false;
    if (!attr_set) {
        cudaFuncSetAttribute(sigmoid_flow_kernel,
                             cudaFuncAttributeMaxDynamicSharedMemorySize,
                             smem_bytes);
        attr_set = true;
    }

    sigmoid_flow_kernel<<<B, THREADS, smem_bytes>>>(
        x, logdet_in, dsp, out_xnew, out_logdet, D);
}

// round 12
// speedup vs baseline: 1.0007x; 1.0007x over previous
#include <cuda_runtime.h>
#include <cstdint>

// SigmoidFlow, quad-split compute + cp.async double-buffered SMEM pipeline.
//
// Math (linear-domain collapse of the reference):
//   logj = log( sum_k e_k * a_k * s_k(1-s_k) ) - log( sum_k e_k ), e_k=exp(wl_k)
//   s(1-s) = u*r^2, u = exp(-|pre|), r = 1/(1+u)  (both signs).
//
// R10: dsparams streamed gmem->smem with cp.async.cg (deep MLP independent of
// register file, perfectly coalesced), 2-stage double buffer, compute reads
// tiles from SMEM. 4 threads cooperate per element (4 k's each).

#define NDIM 16
#define DELTA_F 1e-6f
#define LOG1MDELTA (-1.0000005e-6f)   // log(1 - 1e-6)

#define TILE_ELEMS 128
#define TILE_F4    (TILE_ELEMS * 12)   // 1536 float4 = 24 KB
#define THREADS    512

__device__ __forceinline__ void cp_async16(uint32_t dst_smem, const float4* src) {
    asm volatile("cp.async.cg.shared.global [%0], [%1], 16;"
                 :: "r"(dst_smem), "l"(src));
}
__device__ __forceinline__ void cp_commit() {
    asm volatile("cp.async.commit_group;");
}
__device__ __forceinline__ void cp_wait1() {
    asm volatile("cp.async.wait_group 1;");
}
__device__ __forceinline__ void cp_wait0() {
    asm volatile("cp.async.wait_group 0;");
}

__global__ __launch_bounds__(THREADS, 3)
void sigmoid_flow_kernel(const float* __restrict__ x,
                         const float* __restrict__ logdet_in,
                         const float* __restrict__ dsp,
                         float* __restrict__ out_xnew,
                         float* __restrict__ out_logdet,
                         int D)
{
    extern __shared__ float4 sbuf[];          // 2 * TILE_F4 float4s
    __shared__ float sred[16];

    const int b = blockIdx.x;
    const int t = threadIdx.x;
    const int q = t >> 2;                     // element slot in tile (0..127)
    const int c = t & 3;                      // float4 chunk of element (0..3)
    const int ntiles = D / TILE_ELEMS;        // 4 for D=512

    const float4* __restrict__ dsp4 = reinterpret_cast<const float4*>(dsp);
    const uint32_t smem_base = (uint32_t)__cvta_generic_to_shared(sbuf);

    // ---- stage a tile of dsparams into smem buffer (coalesced, async) ----
    auto stage = [&](int tile, int bufsel) {
        const float4* src = dsp4 + (long long)(b * D + tile * TILE_ELEMS) * 12;
        const uint32_t dst = smem_base + (uint32_t)bufsel * (TILE_F4 * 16);
#pragma unroll
        for (int i = 0; i < TILE_F4 / THREADS; i++) {
            const int idx = t + i * THREADS;
            cp_async16(dst + idx * 16, src + idx);
        }
        cp_commit();
    };

    // prologue: prefetch tiles 0 and 1
    stage(0, 0);
    if (ntiles > 1) stage(1, 1);

    float ldsum = 0.0f;

    for (int tile = 0; tile < ntiles; tile++) {
        if (tile + 2 <= ntiles) cp_wait1(); else cp_wait0();
        __syncthreads();

        const float4* buf = sbuf + (tile & 1) * TILE_F4;
        const int e = b * D + tile * TILE_ELEMS + q;

        const float4 va = buf[q * 12 + c];
        const float4 vb = buf[q * 12 + 4 + c];
        const float4 vw = buf[q * 12 + 8 + c];
        const float xv = x[e];

        const float zs[4] = {va.x, va.y, va.z, va.w};
        const float bs[4] = {vb.x, vb.y, vb.z, vb.w};
        const float ws[4] = {vw.x, vw.y, vw.z, vw.w};

        float Se = 0.0f, S1 = 0.0f, S2 = 0.0f;
#pragma unroll
        for (int j = 0; j < 4; j++) {
            // a = softplus(z), numerically stable
            const float z = zs[j];
            const float tt = __expf(-fabsf(z));
            const float a = fmaxf(z, 0.0f) + __logf(1.0f + tt);

            // sigmoid terms via shared exp(-|pre|)
            const float pre = fmaf(a, xv, bs[j]);
            const float u = __expf(-fabsf(pre));
            const float r = __fdividef(1.0f, 1.0f + u);
            const float s = (pre > 0.0f) ? r : u * r;  // sigmoid(pre)
            const float ss = u * r * r;                // sigm(pre)*sigm(-pre)

            const float ek = __expf(ws[j]);            // unnormalized softmax

            Se += ek;
            S1 = fmaf(ek, s, S1);
            S2 = fmaf(ek * a, ss, S2);
        }

        // reduce the three sums across the quad
        Se += __shfl_xor_sync(0xffffffffu, Se, 1);
        Se += __shfl_xor_sync(0xffffffffu, Se, 2);
        S1 += __shfl_xor_sync(0xffffffffu, S1, 1);
        S1 += __shfl_xor_sync(0xffffffffu, S1, 2);
        S2 += __shfl_xor_sync(0xffffffffu, S2, 1);
        S2 += __shfl_xor_sync(0xffffffffu, S2, 2);

        // epilogue: computed by all quad lanes (no divergence), stored by c==0
        const float invSe = __fdividef(1.0f, Se);
        const float x_pre = S1 * invSe;
        const float xpc = fmaf(x_pre, 1.0f - DELTA_F, 0.5f * DELTA_F);
        const float lx  = __logf(xpc);
        const float l1x = __logf(1.0f - xpc);
        const float logj = __logf(S2 * invSe);

        if (c == 0) {
            out_xnew[e] = lx - l1x;
            ldsum += logj + LOG1MDELTA - lx - l1x;
        }

        __syncthreads();   // all reads of buf done before it is re-staged
        if (tile + 2 < ntiles) stage(tile + 2, tile & 1);
    }

    // ---- deterministic block reduction for logdet (no float atomics) ----
    const int lane = t & 31;
    const int warp = t >> 5;
#pragma unroll
    for (int o = 16; o > 0; o >>= 1)
        ldsum += __shfl_xor_sync(0xffffffffu, ldsum, o);

    if (lane == 0) sred[warp] = ldsum;
    __syncthreads();

    if (warp == 0) {
        float v = (lane < 16) ? sred[lane] : 0.0f;
#pragma unroll
        for (int o = 16; o > 0; o >>= 1)
            v += __shfl_xor_sync(0xffffffffu, v, o);
        if (lane == 0)
            out_logdet[b] = v + logdet_in[b];
    }
}

extern "C" void kernel_launch(void* const* d_in, const int* in_sizes, int n_in,
                              void* d_out, int out_size)
{
    const float* x         = (const float*)d_in[0];   // (B, D)
    const float* logdet_in = (const float*)d_in[1];   // (B,)
    const float* dsp       = (const float*)d_in[2];   // (B, D, 3*NDIM)

    const int B = in_sizes[1];
    const int D = in_sizes[0] / B;   // 512

    float* out_xnew   = (float*)d_out;                      // (B, D)
    float* out_logdet = (float*)d_out + (size_t)B * D;      // (B,)

    const int smem_bytes = 2 * TILE_F4 * (int)sizeof(float4);   // 49152
    static bool attr_set = false;
    if (!attr_set) {
        cudaFuncSetAttribute(sigmoid_flow_kernel,
                             cudaFuncAttributeMaxDynamicSharedMemorySize,
                             smem_bytes);
        attr_set = true;
    }

    sigmoid_flow_kernel<<<B, THREADS, smem_bytes>>>(
        x, logdet_in, dsp, out_xnew, out_logdet, D);
}